// round 4
// baseline (speedup 1.0000x reference)
#include <cuda_runtime.h>
#include <cuda_bf16.h>

// y = x @ (A@B)^T + bias  ==  T = x@B^T (32x64);  y = T@A^T + bias
// x: [32,8192] f32, A: [8192,64] f32, B: [64,8192] f32, bias: [8192] f32
// Single fused persistent kernel, 128 blocks (all co-resident on 148 SMs),
// software grid barriers with a monotonic ticket counter (replay-safe).

#define BATCH 32
#define IN_F  8192
#define OUT_F 8192
#define RANK  64
#define GRID  128
#define TPB   256
#define S1_CHUNK 64   // IN_F / GRID
#define OTILE    64   // OUT_F / GRID

__device__ float        g_T[BATCH * RANK];
__device__ unsigned int g_bar;   // monotonic ticket counter; never reset

__device__ __forceinline__ void grid_barrier() {
    __syncthreads();
    if (threadIdx.x == 0) {
        __threadfence();                                   // release
        unsigned ticket = atomicAdd(&g_bar, 1u);
        unsigned target = (ticket / GRID + 1u) * GRID;
        while (*(volatile unsigned*)&g_bar < target) { }
        __threadfence();                                   // acquire
    }
    __syncthreads();
}

__global__ __launch_bounds__(TPB, 1)
void lowrank_fused_kernel(const float* __restrict__ x,
                          const float* __restrict__ A,
                          const float* __restrict__ Bm,
                          const float* __restrict__ bias,
                          float* __restrict__ y) {
    // A_s + bias_s live across the whole kernel (prefetched for phase 2).
    __shared__ float A_s[OTILE][RANK + 4];
    __shared__ float bias_s[OTILE];
    __shared__ union {
        struct {
            float x_s[BATCH][S1_CHUNK + 4];
            float B_s[RANK][S1_CHUNK + 4];
        } p1;
        float T_s[BATCH][RANK + 4];
    } u;

    const int tid = threadIdx.x;
    const int blk = blockIdx.x;
    const int k0  = blk * S1_CHUNK;   // K-chunk owned in phase 1
    const int o0  = blk * OTILE;      // output tile owned in phase 2

    // ---- Zero this block's slice of g_T (16 elements; 128*16 = 2048) ----
    if (tid < 16) g_T[blk * 16 + tid] = 0.0f;

    // ---- Phase-1 tile loads: x[32][64], B[64][64] ----
    #pragma unroll
    for (int i = 0; i < 2; i++) {
        int idx = tid + i * 256;                 // 0..511
        int b  = idx >> 4;                       // 16 float4 per row
        int jj = idx & 15;
        float4 v = reinterpret_cast<const float4*>(x + b * IN_F + k0)[jj];
        *reinterpret_cast<float4*>(&u.p1.x_s[b][jj * 4]) = v;
    }
    #pragma unroll
    for (int i = 0; i < 4; i++) {
        int idx = tid + i * 256;                 // 0..1023
        int r  = idx >> 4;
        int jj = idx & 15;
        float4 v = reinterpret_cast<const float4*>(Bm + r * IN_F + k0)[jj];
        *reinterpret_cast<float4*>(&u.p1.B_s[r][jj * 4]) = v;
    }
    // ---- Prefetch phase-2 operands (A tile 64x64, bias 64) now, so the
    //      DRAM traffic overlaps phase-1 compute + barrier waits. ----
    #pragma unroll
    for (int i = 0; i < 4; i++) {
        int idx = tid + i * 256;
        int o  = idx >> 4;
        int jj = idx & 15;
        float4 v = reinterpret_cast<const float4*>(A + (o0 + o) * RANK)[jj];
        *reinterpret_cast<float4*>(&A_s[o][jj * 4]) = v;
    }
    if (tid < OTILE) bias_s[tid] = bias[o0 + tid];
    __syncthreads();

    // ---- Phase 1 compute: partial T[b][r] over this K chunk ----
    const int r  = tid & 63;
    const int b0 = (tid >> 6) * 8;               // 8 batch rows per thread

    float acc[8];
    #pragma unroll
    for (int j = 0; j < 8; j++) acc[j] = 0.0f;

    #pragma unroll
    for (int k4 = 0; k4 < S1_CHUNK / 4; k4++) {
        float4 bv = *reinterpret_cast<const float4*>(&u.p1.B_s[r][k4 * 4]);
        #pragma unroll
        for (int j = 0; j < 8; j++) {
            float4 xv = *reinterpret_cast<const float4*>(&u.p1.x_s[b0 + j][k4 * 4]);
            acc[j] += bv.x * xv.x;
            acc[j] += bv.y * xv.y;
            acc[j] += bv.z * xv.z;
            acc[j] += bv.w * xv.w;
        }
    }

    // Barrier #1: ensures all blocks' zero-stores of g_T are visible before
    // any atomics. Arrival is after phase-1 compute, so the wait is hidden.
    grid_barrier();

    #pragma unroll
    for (int j = 0; j < 8; j++)
        atomicAdd(&g_T[(b0 + j) * RANK + r], acc[j]);

    // Barrier #2: all atomics done -> T complete.
    grid_barrier();

    // ---- Phase 2: load T (2048 floats) into smem, y = T @ A^T + bias ----
    #pragma unroll
    for (int i = 0; i < 2; i++) {
        int idx = tid + i * 256;                 // 0..511
        int b  = idx >> 4;
        int jj = idx & 15;
        float4 v = __ldcg(reinterpret_cast<const float4*>(g_T + b * RANK) + jj);
        *reinterpret_cast<float4*>(&u.T_s[b][jj * 4]) = v;
    }
    __syncthreads();

    const int o = tid & 63;                      // output col within tile
    float acc2[8];
    #pragma unroll
    for (int j = 0; j < 8; j++) acc2[j] = 0.0f;

    #pragma unroll
    for (int r4 = 0; r4 < RANK / 4; r4++) {
        float4 av = *reinterpret_cast<const float4*>(&A_s[o][r4 * 4]);
        #pragma unroll
        for (int j = 0; j < 8; j++) {
            float4 tv = *reinterpret_cast<const float4*>(&u.T_s[b0 + j][r4 * 4]);
            acc2[j] += av.x * tv.x;
            acc2[j] += av.y * tv.y;
            acc2[j] += av.z * tv.z;
            acc2[j] += av.w * tv.w;
        }
    }

    const float bv = bias_s[o];
    #pragma unroll
    for (int j = 0; j < 8; j++)
        y[(b0 + j) * OUT_F + o0 + o] = acc2[j] + bv;
}

extern "C" void kernel_launch(void* const* d_in, const int* in_sizes, int n_in,
                              void* d_out, int out_size) {
    const float* x    = (const float*)d_in[0];   // [32, 8192]
    const float* A    = (const float*)d_in[1];   // [8192, 64]
    const float* Bm   = (const float*)d_in[2];   // [64, 8192]
    const float* bias = (const float*)d_in[3];   // [8192]
    float* y = (float*)d_out;                    // [32, 8192]

    lowrank_fused_kernel<<<GRID, TPB>>>(x, A, Bm, bias, y);
}

// round 6
// speedup vs baseline: 1.0677x; 1.0677x over previous
#include <cuda_runtime.h>
#include <cuda_bf16.h>

// y = x @ (A@B)^T + bias  ==  T = x@B^T (32x64);  y = T@A^T + bias
// Single fused persistent kernel, 128 blocks x 512 threads, software grid
// barriers (release/acquire atomics + backoff), packed f32x2 FMA everywhere.

#define BATCH 32
#define IN_F  8192
#define OUT_F 8192
#define RANK  64
#define GRID  128
#define TPB   512
#define S1_CHUNK 64   // IN_F / GRID
#define OTILE    64   // OUT_F / GRID

__device__ float        g_T[BATCH * RANK];
__device__ unsigned int g_bar;   // monotonic ticket counter; never reset

// Packed fp32x2 helpers (sm_103a; FFMA2 only reachable via PTX)
#define FMA2(acc, a, b) \
    asm("fma.rn.f32x2 %0, %1, %2, %0;" : "+l"(acc) : "l"(a), "l"(b))
#define ADD2(d, a, b) \
    asm("add.rn.f32x2 %0, %1, %2;" : "=l"(d) : "l"(a), "l"(b))

__device__ __forceinline__ float hsum2(unsigned long long v) {
    float lo, hi;
    asm("mov.b64 {%0, %1}, %2;" : "=f"(lo), "=f"(hi) : "l"(v));
    return lo + hi;
}

__device__ __forceinline__ void grid_barrier() {
    __syncthreads();
    if (threadIdx.x == 0) {
        unsigned ticket;
        // release-arrive: orders all prior writes of this block
        asm volatile("atom.release.gpu.global.add.u32 %0, [%1], %2;"
                     : "=r"(ticket) : "l"(&g_bar), "r"(1u) : "memory");
        unsigned target = (ticket / GRID + 1u) * GRID;
        for (;;) {
            unsigned v;
            asm volatile("ld.acquire.gpu.global.u32 %0, [%1];"
                         : "=r"(v) : "l"(&g_bar) : "memory");
            if (v >= target) break;
            __nanosleep(64);   // backoff: don't hammer L2 while waiting
        }
    }
    __syncthreads();
}

__global__ __launch_bounds__(TPB, 1)
void lowrank_fused_kernel(const float* __restrict__ x,
                          const float* __restrict__ A,
                          const float* __restrict__ Bm,
                          const float* __restrict__ bias,
                          float* __restrict__ y) {
    __shared__ __align__(16) float A_s[OTILE][RANK + 4];
    __shared__ float bias_s[OTILE];
    __shared__ __align__(16) union SU {
        struct {
            float x_s[BATCH][S1_CHUNK + 4];
            float B_s[RANK][S1_CHUNK + 4];
        } p1;
        float T_s[BATCH][RANK + 4];
    } u;

    const int tid = threadIdx.x;
    const int blk = blockIdx.x;
    const int k0  = blk * S1_CHUNK;
    const int o0  = blk * OTILE;

    // Zero this block's 16-element slice of g_T (ordered by barrier #1).
    if (tid < 16) g_T[blk * 16 + tid] = 0.0f;

    // ---- Phase-1 tile loads: x[32][64] (512 float4), B[64][64] (1024) ----
    {
        int b  = tid >> 4;            // 0..31
        int jj = tid & 15;
        float4 v = reinterpret_cast<const float4*>(x + b * IN_F + k0)[jj];
        *reinterpret_cast<float4*>(&u.p1.x_s[b][jj * 4]) = v;
    }
    #pragma unroll
    for (int i = 0; i < 2; i++) {
        int idx = tid + i * TPB;      // 0..1023
        int r  = idx >> 4;
        int jj = idx & 15;
        float4 v = reinterpret_cast<const float4*>(Bm + r * IN_F + k0)[jj];
        *reinterpret_cast<float4*>(&u.p1.B_s[r][jj * 4]) = v;
    }
    // ---- Prefetch phase-2 operands (overlaps phase-1 compute + barriers) ----
    #pragma unroll
    for (int i = 0; i < 2; i++) {
        int idx = tid + i * TPB;
        int o  = idx >> 4;
        int jj = idx & 15;
        float4 v = reinterpret_cast<const float4*>(A + (o0 + o) * RANK)[jj];
        *reinterpret_cast<float4*>(&A_s[o][jj * 4]) = v;
    }
    if (tid < OTILE) bias_s[tid] = bias[o0 + tid];
    __syncthreads();

    // ---- Phase 1: partial T[b][r] over this K chunk, packed along k ----
    const int r  = tid & 63;
    const int b0 = (tid >> 6) * 4;    // 4 batch rows per thread

    unsigned long long acc[4][2];
    #pragma unroll
    for (int j = 0; j < 4; j++) { acc[j][0] = 0ull; acc[j][1] = 0ull; }

    #pragma unroll
    for (int k4 = 0; k4 < S1_CHUNK / 4; k4++) {
        ulonglong2 bv = *reinterpret_cast<const ulonglong2*>(&u.p1.B_s[r][k4 * 4]);
        #pragma unroll
        for (int j = 0; j < 4; j++) {
            ulonglong2 xv = *reinterpret_cast<const ulonglong2*>(&u.p1.x_s[b0 + j][k4 * 4]);
            FMA2(acc[j][0], xv.x, bv.x);
            FMA2(acc[j][1], xv.y, bv.y);
        }
    }

    // Barrier #1: all zero-stores visible before any atomic accumulation.
    grid_barrier();

    #pragma unroll
    for (int j = 0; j < 4; j++) {
        unsigned long long s;
        ADD2(s, acc[j][0], acc[j][1]);
        atomicAdd(&g_T[(b0 + j) * RANK + r], hsum2(s));   // emitted as REDG
    }

    // Barrier #2: T complete.
    grid_barrier();

    // ---- Phase 2: T (512 float4) -> smem, y = T @ A^T + bias ----
    {
        int b  = tid >> 4;
        int jj = tid & 15;
        float4 v = __ldcg(reinterpret_cast<const float4*>(g_T + b * RANK) + jj);
        *reinterpret_cast<float4*>(&u.T_s[b][jj * 4]) = v;
    }
    __syncthreads();

    const int o = tid & 63;
    unsigned long long acc2[4][2];
    #pragma unroll
    for (int j = 0; j < 4; j++) { acc2[j][0] = 0ull; acc2[j][1] = 0ull; }

    #pragma unroll
    for (int r4 = 0; r4 < RANK / 4; r4++) {
        ulonglong2 av = *reinterpret_cast<const ulonglong2*>(&A_s[o][r4 * 4]);
        #pragma unroll
        for (int j = 0; j < 4; j++) {
            ulonglong2 tv = *reinterpret_cast<const ulonglong2*>(&u.T_s[b0 + j][r4 * 4]);
            FMA2(acc2[j][0], tv.x, av.x);
            FMA2(acc2[j][1], tv.y, av.y);
        }
    }

    const float bv = bias_s[o];
    #pragma unroll
    for (int j = 0; j < 4; j++) {
        unsigned long long s;
        ADD2(s, acc2[j][0], acc2[j][1]);
        y[(b0 + j) * OUT_F + o0 + o] = hsum2(s) + bv;
    }
}

extern "C" void kernel_launch(void* const* d_in, const int* in_sizes, int n_in,
                              void* d_out, int out_size) {
    const float* x    = (const float*)d_in[0];   // [32, 8192]
    const float* A    = (const float*)d_in[1];   // [8192, 64]
    const float* Bm   = (const float*)d_in[2];   // [64, 8192]
    const float* bias = (const float*)d_in[3];   // [8192]
    float* y = (float*)d_out;                    // [32, 8192]

    lowrank_fused_kernel<<<GRID, TPB>>>(x, A, Bm, bias, y);
}

// round 8
// speedup vs baseline: 1.2604x; 1.1805x over previous
#include <cuda_runtime.h>
#include <cuda_bf16.h>

// y = x @ (A@B)^T + bias  ==  T = x@B^T (32x64);  y = T@A^T + bias
// Fused persistent kernel: 128 blocks x 512 threads.
// - XOR-swizzled conflict-free smem tiles (no padding)
// - 2r x 2b register blocking, packed f32x2 FMA
// - red.global.add.v2.f32 accumulation of T
// - grid barrier #1 split (arrive early / wait late), #2 standard

#define BATCH 32
#define IN_F  8192
#define OUT_F 8192
#define RANK  64
#define GRID  128
#define TPB   512
#define S1_CHUNK 64
#define OTILE    64

__device__ float        g_T[BATCH * RANK];
__device__ unsigned int g_bar;   // monotonic ticket counter; never reset

#define FMA2(acc, a, b) \
    asm("fma.rn.f32x2 %0, %1, %2, %0;" : "+l"(acc) : "l"(a), "l"(b))
#define ADD2(d, a, b) \
    asm("add.rn.f32x2 %0, %1, %2;" : "=l"(d) : "l"(a), "l"(b))

__device__ __forceinline__ float hsum2(unsigned long long v) {
    float lo, hi;
    asm("mov.b64 {%0, %1}, %2;" : "=f"(lo), "=f"(hi) : "l"(v));
    return lo + hi;
}

__device__ __forceinline__ unsigned bar_arrive() {
    unsigned ticket;
    asm volatile("atom.release.gpu.global.add.u32 %0, [%1], %2;"
                 : "=r"(ticket) : "l"(&g_bar), "r"(1u) : "memory");
    return (ticket / GRID + 1u) * GRID;   // wait target
}

__device__ __forceinline__ void bar_wait(unsigned target) {
    for (;;) {
        unsigned v;
        asm volatile("ld.acquire.gpu.global.u32 %0, [%1];"
                     : "=r"(v) : "l"(&g_bar) : "memory");
        if (v >= target) break;
        __nanosleep(32);
    }
}

// swizzled float4-column: c, r in tile coords (64-float row stride, no pad)
__device__ __forceinline__ int swz(int r, int c) { return c ^ ((r >> 1) & 7); }

__global__ __launch_bounds__(TPB, 1)
void lowrank_fused_kernel(const float* __restrict__ x,
                          const float* __restrict__ A,
                          const float* __restrict__ Bm,
                          const float* __restrict__ bias,
                          float* __restrict__ y) {
    __shared__ __align__(16) float A_s[OTILE * 64];      // swizzled
    __shared__ float bias_s[OTILE];
    __shared__ unsigned bar1_target;
    __shared__ __align__(16) union SU {
        struct {
            float x_s[BATCH * 64];                       // plain
            float B_s[RANK * 64];                        // swizzled
        } p1;
        float T_s[BATCH * 64];                           // plain
    } u;

    const int tid = threadIdx.x;
    const int blk = blockIdx.x;
    const int k0  = blk * S1_CHUNK;
    const int o0  = blk * OTILE;

    // ---- Zero this block's 16-float slice of g_T (done first) ----
    if (tid < 16) g_T[blk * 16 + tid] = 0.0f;

    // ---- Tile loads ----
    {   // x[32][64] : 512 float4, plain layout
        int b = tid >> 4, c = tid & 15;
        float4 v = reinterpret_cast<const float4*>(x + b * IN_F + k0)[c];
        *reinterpret_cast<float4*>(&u.p1.x_s[b * 64 + c * 4]) = v;
    }
    #pragma unroll
    for (int i = 0; i < 2; i++) {   // B[64][64] : 1024 float4, swizzled
        int idx = tid + i * TPB;
        int r = idx >> 4, c = idx & 15;
        float4 v = reinterpret_cast<const float4*>(Bm + r * IN_F + k0)[c];
        *reinterpret_cast<float4*>(&u.p1.B_s[r * 64 + swz(r, c) * 4]) = v;
    }
    #pragma unroll
    for (int i = 0; i < 2; i++) {   // A tile [64][64] : swizzled (for phase 2)
        int idx = tid + i * TPB;
        int r = idx >> 4, c = idx & 15;
        float4 v = reinterpret_cast<const float4*>(A + (o0 + r) * RANK)[c];
        *reinterpret_cast<float4*>(&A_s[r * 64 + swz(r, c) * 4]) = v;
    }
    if (tid < OTILE) bias_s[tid] = bias[o0 + tid];
    __syncthreads();   // zero-stores + tiles visible block-wide

    // Barrier #1 ARRIVE (early): orders all blocks' zero-stores.
    if (tid == 0) bar1_target = bar_arrive();

    // ---- Phase 1: thread owns r-pair (2*rr, 2*rr+1) x b-pair (2*bp, 2*bp+1)
    const int rr = tid & 31;        // r-pair index; lane id within warp
    const int bp = tid >> 5;        // 0..15, constant per warp -> x broadcast

    unsigned long long accA[2][2], accB[2][2];
    #pragma unroll
    for (int j = 0; j < 2; j++)
        #pragma unroll
        for (int i = 0; i < 2; i++) { accA[j][i] = 0ull; accB[j][i] = 0ull; }

    #pragma unroll
    for (int k4 = 0; k4 < 16; k4++) {
        const int bc = swz(2 * rr, k4) * 4;   // same for both rows of the pair
        ulonglong2 bv0 = *reinterpret_cast<const ulonglong2*>(&u.p1.B_s[(2 * rr)     * 64 + bc]);
        ulonglong2 bv1 = *reinterpret_cast<const ulonglong2*>(&u.p1.B_s[(2 * rr + 1) * 64 + bc]);
        #pragma unroll
        for (int j = 0; j < 2; j++) {
            ulonglong2 xv = *reinterpret_cast<const ulonglong2*>(&u.p1.x_s[(2 * bp + j) * 64 + k4 * 4]);
            FMA2(accA[j][0], xv.x, bv0.x);
            FMA2(accB[j][0], xv.y, bv0.y);
            FMA2(accA[j][1], xv.x, bv1.x);
            FMA2(accB[j][1], xv.y, bv1.y);
        }
    }

    // Barrier #1 WAIT (late): hidden under phase-1 compute.
    if (tid == 0) bar_wait(bar1_target);
    __syncthreads();

    // Accumulate T with vector REDs (adjacent r -> v2)
    #pragma unroll
    for (int j = 0; j < 2; j++) {
        unsigned long long s0, s1;
        ADD2(s0, accA[j][0], accB[j][0]);
        ADD2(s1, accA[j][1], accB[j][1]);
        float f0 = hsum2(s0), f1 = hsum2(s1);
        asm volatile("red.global.add.v2.f32 [%0], {%1, %2};"
                     :: "l"(&g_T[(2 * bp + j) * RANK + 2 * rr]),
                        "f"(f0), "f"(f1) : "memory");
    }

    // Barrier #2: T complete.
    __syncthreads();
    if (tid == 0) bar_wait(bar_arrive());
    __syncthreads();

    // ---- Phase 2: T -> smem (plain), y = T @ A^T + bias ----
    {   // 512 float4 loads
        int b = tid >> 4, c = tid & 15;
        float4 v = __ldcg(reinterpret_cast<const float4*>(g_T + b * RANK) + c);
        *reinterpret_cast<float4*>(&u.T_s[b * 64 + c * 4]) = v;
    }
    __syncthreads();

    const int oo = rr;              // o-pair index = lane id
    unsigned long long cA[2][2], cB[2][2];
    #pragma unroll
    for (int j = 0; j < 2; j++)
        #pragma unroll
        for (int i = 0; i < 2; i++) { cA[j][i] = 0ull; cB[j][i] = 0ull; }

    #pragma unroll
    for (int r4 = 0; r4 < 16; r4++) {
        const int ac = swz(2 * oo, r4) * 4;
        ulonglong2 av0 = *reinterpret_cast<const ulonglong2*>(&A_s[(2 * oo)     * 64 + ac]);
        ulonglong2 av1 = *reinterpret_cast<const ulonglong2*>(&A_s[(2 * oo + 1) * 64 + ac]);
        #pragma unroll
        for (int j = 0; j < 2; j++) {
            ulonglong2 tv = *reinterpret_cast<const ulonglong2*>(&u.T_s[(2 * bp + j) * 64 + r4 * 4]);
            FMA2(cA[j][0], tv.x, av0.x);
            FMA2(cB[j][0], tv.y, av0.y);
            FMA2(cA[j][1], tv.x, av1.x);
            FMA2(cB[j][1], tv.y, av1.y);
        }
    }

    const float2 bv2 = *reinterpret_cast<const float2*>(&bias_s[2 * oo]);
    #pragma unroll
    for (int j = 0; j < 2; j++) {
        unsigned long long s0, s1;
        ADD2(s0, cA[j][0], cB[j][0]);
        ADD2(s1, cA[j][1], cB[j][1]);
        float2 out;
        out.x = hsum2(s0) + bv2.x;
        out.y = hsum2(s1) + bv2.y;
        *reinterpret_cast<float2*>(&y[(2 * bp + j) * OUT_F + o0 + 2 * oo]) = out;
    }
}

extern "C" void kernel_launch(void* const* d_in, const int* in_sizes, int n_in,
                              void* d_out, int out_size) {
    const float* x    = (const float*)d_in[0];   // [32, 8192]
    const float* A    = (const float*)d_in[1];   // [8192, 64]
    const float* Bm   = (const float*)d_in[2];   // [64, 8192]
    const float* bias = (const float*)d_in[3];   // [8192]
    float* y = (float*)d_out;                    // [32, 8192]

    lowrank_fused_kernel<<<GRID, TPB>>>(x, A, Bm, bias, y);
}